// round 1
// baseline (speedup 1.0000x reference)
#include <cuda_runtime.h>
#include <math.h>

#define Bsz 32768
#define Lsz 2048
#define NGc 4
#define GLc 64
#define NTHREADS 256
#define BPT 8                 // batches per MLP tile
#define ROWS_T (BPT*NGc)      // 32 group-rows per tile
#define NTILES (Bsz/BPT)      // 4096

typedef unsigned long long ull;

struct __align__(16) Smem {
    ulonglong2 w12[64][32];     // [k][jp] = { pack(W1[2jp][k],W1[2jp+1][k]), pack(W2[2jp][k],W2[2jp+1][k]) }
    ull  waTp[64][32];          // [k][jp] = pack(Wa[2jp][k], Wa[2jp+1][k])
    ull  xmTd[64][33];          // [k][row] duplicated pair (v,v), row = batch_local*4+g
    ull  lsumTd[64][33];        // [k][row] duplicated pair
    float xrow[2][Lsz];         // double-buffered streamed row (also reused as 4096-float staging at init)
    float xmaskS[32][68];       // [row][1+j], col 0 and 65 are zero halo
    int   idxS[256];
    ull  bl1p[32], bl2p[32], bap[32];
    float w1n[3]; float b1s;
    float w2n[4][12]; float b2s[4];
};

__device__ __forceinline__ ull pk2(float lo, float hi) {
    ull r; asm("mov.b64 %0,{%1,%2};" : "=l"(r) : "f"(lo), "f"(hi)); return r;
}
__device__ __forceinline__ float2 up2(ull v) {
    float2 r; asm("mov.b64 {%0,%1},%2;" : "=f"(r.x), "=f"(r.y) : "l"(v)); return r;
}
__device__ __forceinline__ void fma2(ull& d, ull a, ull b) {
    asm("fma.rn.f32x2 %0,%1,%2,%0;" : "+l"(d) : "l"(a), "l"(b));
}
__device__ __forceinline__ float tanha(float x) {
    float r; asm("tanh.approx.f32 %0,%1;" : "=f"(r) : "f"(x)); return r;
}
__device__ __forceinline__ float tanh2(float x) { return tanha(tanha(x)); }
__device__ __forceinline__ float sigmoidf(float z) {
    return __fdividef(1.f, 1.f + __expf(-z));
}

__global__ void __launch_bounds__(NTHREADS, 2)
fused_kernel(const float* __restrict__ x, const int* __restrict__ index_all,
             const float* __restrict__ v1, const float* __restrict__ g1, const float* __restrict__ b1,
             const float* __restrict__ v2, const float* __restrict__ g2, const float* __restrict__ b2,
             const float* __restrict__ W1, const float* __restrict__ bl1,
             const float* __restrict__ W2, const float* __restrict__ bl2,
             const float* __restrict__ Wa, const float* __restrict__ ba,
             float* __restrict__ out)
{
    extern __shared__ char smraw[];
    Smem* s = (Smem*)smraw;
    const int t = threadIdx.x;
    float* stage = &s->xrow[0][0];   // 4096 floats of staging

    // ---------------- init: coalesced load -> transpose/pack into SMEM ----------------
    for (int i = t; i < 4096; i += NTHREADS) stage[i] = W1[i];
    __syncthreads();
    for (int p = t; p < 2048; p += NTHREADS) {
        int k = p >> 5, jp = p & 31;
        s->w12[k][jp].x = pk2(stage[(2*jp)*64 + k], stage[(2*jp+1)*64 + k]);
    }
    __syncthreads();
    for (int i = t; i < 4096; i += NTHREADS) stage[i] = W2[i];
    __syncthreads();
    for (int p = t; p < 2048; p += NTHREADS) {
        int k = p >> 5, jp = p & 31;
        s->w12[k][jp].y = pk2(stage[(2*jp)*64 + k], stage[(2*jp+1)*64 + k]);
    }
    __syncthreads();
    for (int i = t; i < 4096; i += NTHREADS) stage[i] = Wa[i];
    __syncthreads();
    for (int p = t; p < 2048; p += NTHREADS) {
        int k = p >> 5, jp = p & 31;
        s->waTp[k][jp] = pk2(stage[(2*jp)*64 + k], stage[(2*jp+1)*64 + k]);
    }
    s->idxS[t] = index_all[t];
    if (t < 32) {
        s->bl1p[t] = pk2(bl1[2*t], bl1[2*t+1]);
        s->bl2p[t] = pk2(bl2[2*t], bl2[2*t+1]);
        s->bap[t]  = pk2(ba[2*t],  ba[2*t+1]);
        s->xmaskS[t][0]  = 0.f;   // conv2 left halo
        s->xmaskS[t][65] = 0.f;   // conv2 right halo
    }
    if (t == 0) {
        float n = sqrtf(v1[0]*v1[0] + v1[1]*v1[1] + v1[2]*v1[2]);
        float gg = g1[0] / n;
        s->w1n[0] = gg*v1[0]; s->w1n[1] = gg*v1[1]; s->w1n[2] = gg*v1[2];
        s->b1s = b1[0];
    }
    if (t < 4) {
        float ss = 0.f;
        #pragma unroll
        for (int m = 0; m < 12; m++) { float vv = v2[t*12+m]; ss += vv*vv; }
        float gg = g2[t] / sqrtf(ss);
        #pragma unroll
        for (int m = 0; m < 12; m++) s->w2n[t][m] = gg * v2[t*12+m];
        s->b2s[t] = b2[t];
    }
    __syncthreads();

    // hoisted per-thread constants
    const float cw0 = s->w1n[0], cw1 = s->w1n[1], cw2 = s->w1n[2], cb = s->b1s;
    const int oo = t >> 6, cc = t & 63;           // conv2 mapping
    float wc[12];
    #pragma unroll
    for (int m = 0; m < 12; m++) wc[m] = s->w2n[oo][m];
    const float b2o = s->b2s[oo];
    const int myIdx = s->idxS[t];
    const int g = t >> 6, kk = t & 63;            // gather mapping
    const int jp = t & 31, r0i = (t >> 5) * 4;    // MLP mapping: column pair jp, rows r0i..r0i+3

    float* out_bag  = out;
    float* out_site = out + (size_t)Bsz * NGc * GLc;

    for (int tile = blockIdx.x; tile < NTILES; tile += gridDim.x) {
        const int b0 = tile * BPT;

        // prologue: stage first row
        {
            const float4* xr = (const float4*)(x + (size_t)b0 * Lsz);
            float4 a = xr[t*2], b = xr[t*2+1];
            ((float4*)s->xrow[0])[t*2]   = a;
            ((float4*)s->xrow[0])[t*2+1] = b;
        }
        __syncthreads();

        // ---- stream 8 rows: conv1 -> x_site, gather -> xmTd ----
        #pragma unroll 1
        for (int sb = 0; sb < BPT; sb++) {
            const int cur = sb & 1;
            float4 p0, p1;
            if (sb < BPT-1) {
                const float4* xn = (const float4*)(x + (size_t)(b0+sb+1) * Lsz);
                p0 = xn[t*2]; p1 = xn[t*2+1];
            }
            {
                const int base = t * 8;
                float4 a = *(const float4*)&s->xrow[cur][base];
                float4 b = *(const float4*)&s->xrow[cur][base+4];
                float e[10];
                e[0] = (t == 0)   ? 0.f : s->xrow[cur][base-1];
                e[1]=a.x; e[2]=a.y; e[3]=a.z; e[4]=a.w;
                e[5]=b.x; e[6]=b.y; e[7]=b.z; e[8]=b.w;
                e[9] = (t == 255) ? 0.f : s->xrow[cur][base+8];
                float r[8];
                #pragma unroll
                for (int q = 0; q < 8; q++)
                    r[q] = tanh2(fmaf(cw0, e[q], fmaf(cw1, e[q+1], fmaf(cw2, e[q+2], cb))));
                float* so = out_site + (size_t)(b0+sb) * Lsz + base;
                *(float4*)so     = make_float4(r[0], r[1], r[2], r[3]);
                *(float4*)(so+4) = make_float4(r[4], r[5], r[6], r[7]);
            }
            {   // gather xm for this batch
                float v = s->xrow[cur][myIdx];
                s->xmTd[kk][sb*4 + g] = pk2(v, v);
            }
            if (sb < BPT-1) {
                ((float4*)s->xrow[1-cur])[t*2]   = p0;
                ((float4*)s->xrow[1-cur])[t*2+1] = p1;
            }
            __syncthreads();
        }

        // ---- phase 1: l1 = relu(xm@W1^T+bl1), l2 = relu(xm@W2^T+bl2), lsum -> SMEM ----
        ull acc1[4], acc2[4];
        {
            ull b1v = s->bl1p[jp], b2v = s->bl2p[jp];
            #pragma unroll
            for (int i = 0; i < 4; i++) { acc1[i] = b1v; acc2[i] = b2v; }
        }
        #pragma unroll 4
        for (int k = 0; k < 64; k++) {
            ulonglong2 w = s->w12[k][jp];
            #pragma unroll
            for (int i = 0; i < 4; i++) {
                ull a = s->xmTd[k][r0i + i];
                fma2(acc1[i], a, w.x);
                fma2(acc2[i], a, w.y);
            }
        }
        #pragma unroll
        for (int i = 0; i < 4; i++) {
            float2 u1 = up2(acc1[i]), u2 = up2(acc2[i]);
            float lo = fmaxf(u1.x, 0.f) + fmaxf(u2.x, 0.f);
            float hi = fmaxf(u1.y, 0.f) + fmaxf(u2.y, 0.f);
            s->lsumTd[2*jp  ][r0i + i] = pk2(lo, lo);
            s->lsumTd[2*jp+1][r0i + i] = pk2(hi, hi);
        }
        __syncthreads();

        // ---- phase 2: A = sigmoid(lsum@Wa^T+ba); xmask = (A+1)*xm -> SMEM ----
        ull accA[4];
        {
            ull bav = s->bap[jp];
            #pragma unroll
            for (int i = 0; i < 4; i++) accA[i] = bav;
        }
        #pragma unroll 4
        for (int k = 0; k < 64; k++) {
            ull w = s->waTp[k][jp];
            #pragma unroll
            for (int i = 0; i < 4; i++) {
                ull a = s->lsumTd[k][r0i + i];
                fma2(accA[i], a, w);
            }
        }
        #pragma unroll
        for (int i = 0; i < 4; i++) {
            float2 z = up2(accA[i]);
            float A0 = sigmoidf(z.x), A1 = sigmoidf(z.y);
            float xm0 = ((const float2*)&s->xmTd[2*jp  ][r0i + i])->x;
            float xm1 = ((const float2*)&s->xmTd[2*jp+1][r0i + i])->x;
            s->xmaskS[r0i + i][1 + 2*jp] = (A0 + 1.f) * xm0;
            s->xmaskS[r0i + i][2 + 2*jp] = (A1 + 1.f) * xm1;
        }
        __syncthreads();

        // ---- phase 3: conv2 + double tanh -> x_bag ----
        #pragma unroll 1
        for (int bo = 0; bo < BPT; bo++) {
            const int rb = bo * 4;
            float acc = b2o;
            #pragma unroll
            for (int i = 0; i < 4; i++)
                #pragma unroll
                for (int d = 0; d < 3; d++)
                    acc = fmaf(wc[i*3 + d], s->xmaskS[rb + i][cc + d], acc);
            out_bag[(size_t)(b0+bo) * (NGc*GLc) + oo*GLc + cc] = tanh2(acc);
        }
        // no trailing sync needed: next-tile prologue __syncthreads orders all reuse
    }
}

extern "C" void kernel_launch(void* const* d_in, const int* in_sizes, int n_in,
                              void* d_out, int out_size)
{
    const float* x   = (const float*)d_in[0];
    const int*   idx = (const int*)  d_in[1];
    const float* v1  = (const float*)d_in[2];
    const float* g1  = (const float*)d_in[3];
    const float* b1  = (const float*)d_in[4];
    const float* v2  = (const float*)d_in[5];
    const float* g2  = (const float*)d_in[6];
    const float* b2  = (const float*)d_in[7];
    const float* W1  = (const float*)d_in[8];
    const float* bl1 = (const float*)d_in[9];
    const float* W2  = (const float*)d_in[10];
    const float* bl2 = (const float*)d_in[11];
    const float* Wa  = (const float*)d_in[12];
    const float* ba  = (const float*)d_in[13];

    cudaFuncSetAttribute(fused_kernel, cudaFuncAttributeMaxDynamicSharedMemorySize,
                         (int)sizeof(Smem));
    fused_kernel<<<304, NTHREADS, sizeof(Smem)>>>(
        x, idx, v1, g1, b1, v2, g2, b2, W1, bl1, W2, bl2, Wa, ba, (float*)d_out);
}

// round 2
// speedup vs baseline: 1.2475x; 1.2475x over previous
#include <cuda_runtime.h>
#include <math.h>

#define Bsz 32768
#define Lsz 2048
#define NGc 4
#define GLc 64
#define NTHREADS 256
#define BPT 16                 // batches per tile
#define ROWS_T (BPT*NGc)       // 64 group-rows per tile
#define PAIRS_T (ROWS_T/2)     // 32 row-pairs
#define NTILES (Bsz/BPT)       // 2048
#define XMOFF 2                // xmask halo offset (keeps STS.64 aligned)

typedef unsigned long long ull;

struct __align__(16) Smem {
    float4 w12n[64][32];     // [k][jp] = {W1[2jp][k],W1[2jp+1][k],W2[2jp][k],W2[2jp+1][k]}  32KB
    float2 waN[64][32];      // [k][jp] = {Wa[2jp][k],Wa[2jp+1][k]}                          16KB
    ull xmPair[64][34];      // [k][p] = pack(xm[2p][k], xm[2p+1][k])                        17.4KB
    union {
        ull  lsumPair[64][34];   // [k][p] = pack(lsum[2p][k], lsum[2p+1][k])
        float xrow[2][Lsz];      // double-buffered streamed row; also init staging
    } u;                                                                                   // 17.4KB
    float xmaskS[ROWS_T][68];  // [row][XMOFF+j]; halo zeros at XMOFF-1 and XMOFF+64       17.4KB
    int   idxS[256];
    float bl1s[64], bl2s[64], bas[64];
    float w1n[3]; float b1s;
    float w2n[4][12]; float b2s[4];
};

__device__ __forceinline__ ull pk2(float lo, float hi) {
    ull r; asm("mov.b64 %0,{%1,%2};" : "=l"(r) : "f"(lo), "f"(hi)); return r;
}
__device__ __forceinline__ float2 up2(ull v) {
    float2 r; asm("mov.b64 {%0,%1},%2;" : "=f"(r.x), "=f"(r.y) : "l"(v)); return r;
}
__device__ __forceinline__ void fma2(ull& d, ull a, ull b) {
    asm("fma.rn.f32x2 %0,%1,%2,%0;" : "+l"(d) : "l"(a), "l"(b));
}
__device__ __forceinline__ float tanha(float x) {
    float r; asm("tanh.approx.f32 %0,%1;" : "=f"(r) : "f"(x)); return r;
}
__device__ __forceinline__ float tanh2(float x) { return tanha(tanha(x)); }
__device__ __forceinline__ float sigmoidf(float z) {
    return __fdividef(1.f, 1.f + __expf(-z));
}

__global__ void __launch_bounds__(NTHREADS, 2)
fused_kernel(const float* __restrict__ x, const int* __restrict__ index_all,
             const float* __restrict__ v1, const float* __restrict__ g1, const float* __restrict__ b1,
             const float* __restrict__ v2, const float* __restrict__ g2, const float* __restrict__ b2,
             const float* __restrict__ W1, const float* __restrict__ bl1,
             const float* __restrict__ W2, const float* __restrict__ bl2,
             const float* __restrict__ Wa, const float* __restrict__ ba,
             float* __restrict__ out)
{
    extern __shared__ char smraw[];
    Smem* s = (Smem*)smraw;
    const int t = threadIdx.x;
    float* stage = &s->u.xrow[0][0];   // 4096 floats staging at init

    // ---------------- init: coalesced load -> transpose into SMEM ----------------
    for (int i = t; i < 4096; i += NTHREADS) stage[i] = W1[i];
    __syncthreads();
    for (int p = t; p < 2048; p += NTHREADS) {
        int k = p >> 5, jp = p & 31;
        s->w12n[k][jp].x = stage[(2*jp)*64 + k];
        s->w12n[k][jp].y = stage[(2*jp+1)*64 + k];
    }
    __syncthreads();
    for (int i = t; i < 4096; i += NTHREADS) stage[i] = W2[i];
    __syncthreads();
    for (int p = t; p < 2048; p += NTHREADS) {
        int k = p >> 5, jp = p & 31;
        s->w12n[k][jp].z = stage[(2*jp)*64 + k];
        s->w12n[k][jp].w = stage[(2*jp+1)*64 + k];
    }
    __syncthreads();
    for (int i = t; i < 4096; i += NTHREADS) stage[i] = Wa[i];
    __syncthreads();
    for (int p = t; p < 2048; p += NTHREADS) {
        int k = p >> 5, jp = p & 31;
        s->waN[k][jp] = make_float2(stage[(2*jp)*64 + k], stage[(2*jp+1)*64 + k]);
    }
    s->idxS[t] = index_all[t];
    if (t < 64) {
        s->bl1s[t] = bl1[t];
        s->bl2s[t] = bl2[t];
        s->bas[t]  = ba[t];
        s->xmaskS[t][XMOFF-1]  = 0.f;     // conv2 left halo
        s->xmaskS[t][XMOFF+64] = 0.f;     // conv2 right halo
    }
    if (t == 0) {
        float n = sqrtf(v1[0]*v1[0] + v1[1]*v1[1] + v1[2]*v1[2]);
        float gg = g1[0] / n;
        s->w1n[0] = gg*v1[0]; s->w1n[1] = gg*v1[1]; s->w1n[2] = gg*v1[2];
        s->b1s = b1[0];
    }
    if (t < 4) {
        float ss = 0.f;
        #pragma unroll
        for (int m = 0; m < 12; m++) { float vv = v2[t*12+m]; ss += vv*vv; }
        float gg = g2[t] / sqrtf(ss);
        #pragma unroll
        for (int m = 0; m < 12; m++) s->w2n[t][m] = gg * v2[t*12+m];
        s->b2s[t] = b2[t];
    }
    __syncthreads();

    // hoisted per-thread constants
    const float cw0 = s->w1n[0], cw1 = s->w1n[1], cw2 = s->w1n[2], cb = s->b1s;
    const int oo = t >> 6, cc = t & 63;            // conv2 mapping
    float wc[12];
    #pragma unroll
    for (int m = 0; m < 12; m++) wc[m] = s->w2n[oo][m];
    const float b2o = s->b2s[oo];
    // gather mapping (threads 0..127): k = t&63, gh = t>>6 in {0,1}
    const int gk = t & 63, gh = (t >> 6) & 1;
    const int gi1 = s->idxS[(2*gh)*64 + gk];
    const int gi2 = s->idxS[(2*gh+1)*64 + gk];
    // MLP mapping: column pair j0=2jp, row-pairs rp0..rp0+3 (8 rows)
    const int jp = t & 31, j0 = 2*jp;
    const int rp0 = (t >> 5) * 4;
    const float bias1 = s->bl1s[j0],   bias1b = s->bl1s[j0+1];
    const float bias2 = s->bl2s[j0],   bias2b = s->bl2s[j0+1];
    const float biasA = s->bas[j0],    biasAb = s->bas[j0+1];

    float* out_bag  = out;
    float* out_site = out + (size_t)Bsz * NGc * GLc;

    for (int tile = blockIdx.x; tile < NTILES; tile += gridDim.x) {
        const int b0 = tile * BPT;

        // prologue: stage first row (regs + SMEM copy for gather/halo)
        float4 ra, rb;
        {
            const float4* xr = (const float4*)(x + (size_t)b0 * Lsz);
            ra = xr[2*t]; rb = xr[2*t+1];
            ((float4*)s->u.xrow[0])[2*t]   = ra;
            ((float4*)s->u.xrow[0])[2*t+1] = rb;
        }
        __syncthreads();

        // ---- stream BPT rows: conv1 -> x_site (from regs), gather -> xmPair ----
        #pragma unroll 1
        for (int sb = 0; sb < BPT; sb++) {
            const int cur = sb & 1;
            float4 p0, p1;
            if (sb < BPT-1) {
                const float4* xn = (const float4*)(x + (size_t)(b0+sb+1) * Lsz);
                p0 = xn[2*t]; p1 = xn[2*t+1];
            }
            {
                const int base = t * 8;
                float e[10];
                e[0] = (t == 0)   ? 0.f : s->u.xrow[cur][base-1];
                e[1]=ra.x; e[2]=ra.y; e[3]=ra.z; e[4]=ra.w;
                e[5]=rb.x; e[6]=rb.y; e[7]=rb.z; e[8]=rb.w;
                e[9] = (t == 255) ? 0.f : s->u.xrow[cur][base+8];
                float r[8];
                #pragma unroll
                for (int q = 0; q < 8; q++)
                    r[q] = tanh2(fmaf(cw0, e[q], fmaf(cw1, e[q+1], fmaf(cw2, e[q+2], cb))));
                float* so = out_site + (size_t)(b0+sb) * Lsz + base;
                *(float4*)so     = make_float4(r[0], r[1], r[2], r[3]);
                *(float4*)(so+4) = make_float4(r[4], r[5], r[6], r[7]);
            }
            if (t < 128) {  // gather two g-rows, pack as row-pair
                float va = s->u.xrow[cur][gi1];
                float vb = s->u.xrow[cur][gi2];
                s->xmPair[gk][sb*2 + gh] = pk2(va, vb);
            }
            if (sb < BPT-1) {
                ((float4*)s->u.xrow[1-cur])[2*t]   = p0;
                ((float4*)s->u.xrow[1-cur])[2*t+1] = p1;
                ra = p0; rb = p1;
            }
            __syncthreads();
        }

        // ---- phase 1: lsum = relu(xm@W1^T+bl1) + relu(xm@W2^T+bl2) ----
        // acc pair = (row 2p, row 2p+1); weights duplicated in regs.
        ull a1a[4], a1b[4], a2a[4], a2b[4];
        #pragma unroll
        for (int i = 0; i < 4; i++) {
            a1a[i] = pk2(bias1, bias1);  a1b[i] = pk2(bias1b, bias1b);
            a2a[i] = pk2(bias2, bias2);  a2b[i] = pk2(bias2b, bias2b);
        }
        #pragma unroll 4
        for (int k = 0; k < 64; k++) {
            float4 wv = s->w12n[k][jp];
            ull w1a = pk2(wv.x, wv.x), w1b = pk2(wv.y, wv.y);
            ull w2a = pk2(wv.z, wv.z), w2b = pk2(wv.w, wv.w);
            ulonglong2 A01 = *(const ulonglong2*)&s->xmPair[k][rp0];
            ulonglong2 A23 = *(const ulonglong2*)&s->xmPair[k][rp0+2];
            fma2(a1a[0], A01.x, w1a); fma2(a1b[0], A01.x, w1b);
            fma2(a2a[0], A01.x, w2a); fma2(a2b[0], A01.x, w2b);
            fma2(a1a[1], A01.y, w1a); fma2(a1b[1], A01.y, w1b);
            fma2(a2a[1], A01.y, w2a); fma2(a2b[1], A01.y, w2b);
            fma2(a1a[2], A23.x, w1a); fma2(a1b[2], A23.x, w1b);
            fma2(a2a[2], A23.x, w2a); fma2(a2b[2], A23.x, w2b);
            fma2(a1a[3], A23.y, w1a); fma2(a1b[3], A23.y, w1b);
            fma2(a2a[3], A23.y, w2a); fma2(a2b[3], A23.y, w2b);
        }
        #pragma unroll
        for (int i = 0; i < 4; i++) {
            float2 u1 = up2(a1a[i]), u2 = up2(a2a[i]);
            s->u.lsumPair[j0][rp0+i] =
                pk2(fmaxf(u1.x,0.f)+fmaxf(u2.x,0.f), fmaxf(u1.y,0.f)+fmaxf(u2.y,0.f));
            float2 v1p = up2(a1b[i]), v2p = up2(a2b[i]);
            s->u.lsumPair[j0+1][rp0+i] =
                pk2(fmaxf(v1p.x,0.f)+fmaxf(v2p.x,0.f), fmaxf(v1p.y,0.f)+fmaxf(v2p.y,0.f));
        }
        __syncthreads();

        // ---- phase 2: A = sigmoid(lsum@Wa^T+ba); xmask = (A+1)*xm ----
        ull aA0[4], aA1[4];
        #pragma unroll
        for (int i = 0; i < 4; i++) { aA0[i] = pk2(biasA, biasA); aA1[i] = pk2(biasAb, biasAb); }
        #pragma unroll 4
        for (int k = 0; k < 64; k++) {
            float2 wv = s->waN[k][jp];
            ull wa0 = pk2(wv.x, wv.x), wa1 = pk2(wv.y, wv.y);
            ulonglong2 A01 = *(const ulonglong2*)&s->u.lsumPair[k][rp0];
            ulonglong2 A23 = *(const ulonglong2*)&s->u.lsumPair[k][rp0+2];
            fma2(aA0[0], A01.x, wa0); fma2(aA1[0], A01.x, wa1);
            fma2(aA0[1], A01.y, wa0); fma2(aA1[1], A01.y, wa1);
            fma2(aA0[2], A23.x, wa0); fma2(aA1[2], A23.x, wa1);
            fma2(aA0[3], A23.y, wa0); fma2(aA1[3], A23.y, wa1);
        }
        #pragma unroll
        for (int i = 0; i < 4; i++) {
            float2 z0 = up2(aA0[i]), z1 = up2(aA1[i]);
            float2 xm0 = up2(s->xmPair[j0][rp0+i]);
            float2 xm1 = up2(s->xmPair[j0+1][rp0+i]);
            int row0 = 2*(rp0+i), row1 = row0+1;
            // per-row store of the two adjacent columns (aligned STS.64)
            *(float2*)&s->xmaskS[row0][XMOFF+j0] =
                make_float2((sigmoidf(z0.x)+1.f)*xm0.x, (sigmoidf(z1.x)+1.f)*xm1.x);
            *(float2*)&s->xmaskS[row1][XMOFF+j0] =
                make_float2((sigmoidf(z0.y)+1.f)*xm0.y, (sigmoidf(z1.y)+1.f)*xm1.y);
        }
        __syncthreads();

        // ---- phase 3: conv2 + double tanh -> x_bag ----
        #pragma unroll 1
        for (int bo = 0; bo < BPT; bo++) {
            const int rbase = bo * 4;
            float acc = b2o;
            #pragma unroll
            for (int i = 0; i < 4; i++)
                #pragma unroll
                for (int d = 0; d < 3; d++)
                    acc = fmaf(wc[i*3 + d], s->xmaskS[rbase + i][XMOFF + cc - 1 + d], acc);
            out_bag[(size_t)(b0+bo) * (NGc*GLc) + oo*GLc + cc] = tanh2(acc);
        }
        __syncthreads();   // protect xmaskS / xmPair before next tile overwrites
    }
}

extern "C" void kernel_launch(void* const* d_in, const int* in_sizes, int n_in,
                              void* d_out, int out_size)
{
    const float* x   = (const float*)d_in[0];
    const int*   idx = (const int*)  d_in[1];
    const float* v1  = (const float*)d_in[2];
    const float* g1  = (const float*)d_in[3];
    const float* b1  = (const float*)d_in[4];
    const float* v2  = (const float*)d_in[5];
    const float* g2  = (const float*)d_in[6];
    const float* b2  = (const float*)d_in[7];
    const float* W1  = (const float*)d_in[8];
    const float* bl1 = (const float*)d_in[9];
    const float* W2  = (const float*)d_in[10];
    const float* bl2 = (const float*)d_in[11];
    const float* Wa  = (const float*)d_in[12];
    const float* ba  = (const float*)d_in[13];

    cudaFuncSetAttribute(fused_kernel, cudaFuncAttributeMaxDynamicSharedMemorySize,
                         (int)sizeof(Smem));
    fused_kernel<<<296, NTHREADS, sizeof(Smem)>>>(
        x, idx, v1, g1, b1, v2, g2, b2, W1, bl1, W2, bl2, Wa, ba, (float*)d_out);
}

// round 3
// speedup vs baseline: 1.2836x; 1.0289x over previous
#include <cuda_runtime.h>
#include <math.h>

#define Bsz 32768
#define Lsz 2048
#define NGc 4
#define GLc 64
#define NTHREADS 256
#define BPT 16                 // batches per tile
#define ROWS_T (BPT*NGc)       // 64 group-rows per tile
#define NTILES (Bsz/BPT)       // 2048

typedef unsigned long long ull;

struct __align__(16) Smem {
    float4 w12n[64][32];     // [k][jp] = {W1[2jp][k],W1[2jp+1][k],W2[2jp][k],W2[2jp+1][k]}  32KB
    float2 waN[64][32];      // [k][jp] = {Wa[2jp][k],Wa[2jp+1][k]}                          16KB
    ull xmPair[64][34];      // [k][p] = pack(xm[2p][k], xm[2p+1][k])                        17.4KB
    union {
        ull  lsumPair[64][34];   // [k][p] = pack(lsum[2p][k], lsum[2p+1][k])
        float xrow[2][Lsz];      // double-buffered streamed row; also init staging
    } u;                                                                                   // 17.4KB
    int   idxS[256];
    float bl1s[64], bl2s[64], bas[64];
    float w1n[3]; float b1s;
    float w2n[4][12]; float b2s[4];
};

__device__ __forceinline__ ull pk2(float lo, float hi) {
    ull r; asm("mov.b64 %0,{%1,%2};" : "=l"(r) : "f"(lo), "f"(hi)); return r;
}
__device__ __forceinline__ float2 up2(ull v) {
    float2 r; asm("mov.b64 {%0,%1},%2;" : "=f"(r.x), "=f"(r.y) : "l"(v)); return r;
}
__device__ __forceinline__ void fma2(ull& d, ull a, ull b) {
    asm("fma.rn.f32x2 %0,%1,%2,%0;" : "+l"(d) : "l"(a), "l"(b));
}
__device__ __forceinline__ float tanha(float x) {
    float r; asm("tanh.approx.f32 %0,%1;" : "=f"(r) : "f"(x)); return r;
}
__device__ __forceinline__ float tanh2(float x) { return tanha(tanha(x)); }
__device__ __forceinline__ float sigmoidf(float z) {
    return __fdividef(1.f, 1.f + __expf(-z));
}

__global__ void __launch_bounds__(NTHREADS, 2)
fused_kernel(const float* __restrict__ x, const int* __restrict__ index_all,
             const float* __restrict__ v1, const float* __restrict__ g1, const float* __restrict__ b1,
             const float* __restrict__ v2, const float* __restrict__ g2, const float* __restrict__ b2,
             const float* __restrict__ W1, const float* __restrict__ bl1,
             const float* __restrict__ W2, const float* __restrict__ bl2,
             const float* __restrict__ Wa, const float* __restrict__ ba,
             float* __restrict__ out)
{
    extern __shared__ char smraw[];
    Smem* s = (Smem*)smraw;
    const int t = threadIdx.x;
    const int lane = t & 31;
    float* stage = &s->u.xrow[0][0];   // 4096 floats staging at init

    // ---------------- init: coalesced load -> transpose into SMEM ----------------
    for (int i = t; i < 4096; i += NTHREADS) stage[i] = W1[i];
    __syncthreads();
    for (int p = t; p < 2048; p += NTHREADS) {
        int k = p >> 5, jp = p & 31;
        s->w12n[k][jp].x = stage[(2*jp)*64 + k];
        s->w12n[k][jp].y = stage[(2*jp+1)*64 + k];
    }
    __syncthreads();
    for (int i = t; i < 4096; i += NTHREADS) stage[i] = W2[i];
    __syncthreads();
    for (int p = t; p < 2048; p += NTHREADS) {
        int k = p >> 5, jp = p & 31;
        s->w12n[k][jp].z = stage[(2*jp)*64 + k];
        s->w12n[k][jp].w = stage[(2*jp+1)*64 + k];
    }
    __syncthreads();
    for (int i = t; i < 4096; i += NTHREADS) stage[i] = Wa[i];
    __syncthreads();
    for (int p = t; p < 2048; p += NTHREADS) {
        int k = p >> 5, jp = p & 31;
        s->waN[k][jp] = make_float2(stage[(2*jp)*64 + k], stage[(2*jp+1)*64 + k]);
    }
    s->idxS[t] = index_all[t];
    if (t < 64) {
        s->bl1s[t] = bl1[t];
        s->bl2s[t] = bl2[t];
        s->bas[t]  = ba[t];
    }
    if (t == 0) {
        float n = sqrtf(v1[0]*v1[0] + v1[1]*v1[1] + v1[2]*v1[2]);
        float gg = g1[0] / n;
        s->w1n[0] = gg*v1[0]; s->w1n[1] = gg*v1[1]; s->w1n[2] = gg*v1[2];
        s->b1s = b1[0];
    }
    if (t < 4) {
        float ss = 0.f;
        #pragma unroll
        for (int m = 0; m < 12; m++) { float vv = v2[t*12+m]; ss += vv*vv; }
        float gg = g2[t] / sqrtf(ss);
        #pragma unroll
        for (int m = 0; m < 12; m++) s->w2n[t][m] = gg * v2[t*12+m];
        s->b2s[t] = b2[t];
    }
    __syncthreads();

    // hoisted per-thread constants
    const float cw0 = s->w1n[0], cw1 = s->w1n[1], cw2 = s->w1n[2], cb = s->b1s;
    // gather mapping (threads 0..127): k = t&63, gh = t>>6 in {0,1}
    const int gk = t & 63, gh = (t >> 6) & 1;
    const int gi1 = s->idxS[(2*gh)*64 + gk];
    const int gi2 = s->idxS[(2*gh+1)*64 + gk];
    // MLP mapping: column pair j0=2jp, row-pairs rp0..rp0+3 (8 rows = 2 batches x 4 g)
    const int jp = lane, j0 = 2*jp;
    const int rp0 = (t >> 5) * 4;
    const float bias1 = s->bl1s[j0],   bias1b = s->bl1s[j0+1];
    const float bias2 = s->bl2s[j0],   bias2b = s->bl2s[j0+1];
    const float biasA = s->bas[j0],    biasAb = s->bas[j0+1];

    float* out_bag  = out;
    float* out_site = out + (size_t)Bsz * NGc * GLc;

    for (int tile = blockIdx.x; tile < NTILES; tile += gridDim.x) {
        const int b0 = tile * BPT;

        // prologue: stage first row (regs + SMEM copy for gather/halo)
        float4 ra, rb;
        {
            const float4* xr = (const float4*)(x + (size_t)b0 * Lsz);
            ra = xr[2*t]; rb = xr[2*t+1];
            ((float4*)s->u.xrow[0])[2*t]   = ra;
            ((float4*)s->u.xrow[0])[2*t+1] = rb;
        }
        __syncthreads();

        // ---- stream BPT rows: conv1 -> x_site (regs + shuffles), gather -> xmPair ----
        #pragma unroll 1
        for (int sb = 0; sb < BPT; sb++) {
            const int cur = sb & 1;
            float4 p0, p1;
            if (sb < BPT-1) {
                const float4* xn = (const float4*)(x + (size_t)(b0+sb+1) * Lsz);
                p0 = xn[2*t]; p1 = xn[2*t+1];
            }
            {
                const int base = t * 8;
                // halo via intra-warp shuffle; only warp-edge lanes touch SMEM
                float em1 = __shfl_up_sync(0xffffffffu, rb.w, 1);
                float ep8 = __shfl_down_sync(0xffffffffu, ra.x, 1);
                if (lane == 0)  em1 = (t == 0)   ? 0.f : s->u.xrow[cur][base-1];
                if (lane == 31) ep8 = (t == 255) ? 0.f : s->u.xrow[cur][base+8];
                float e[10];
                e[0]=em1;
                e[1]=ra.x; e[2]=ra.y; e[3]=ra.z; e[4]=ra.w;
                e[5]=rb.x; e[6]=rb.y; e[7]=rb.z; e[8]=rb.w;
                e[9]=ep8;
                float r[8];
                #pragma unroll
                for (int q = 0; q < 8; q++)
                    r[q] = tanh2(fmaf(cw0, e[q], fmaf(cw1, e[q+1], fmaf(cw2, e[q+2], cb))));
                float* so = out_site + (size_t)(b0+sb) * Lsz + base;
                *(float4*)so     = make_float4(r[0], r[1], r[2], r[3]);
                *(float4*)(so+4) = make_float4(r[4], r[5], r[6], r[7]);
            }
            if (t < 128) {  // gather two g-rows, pack as row-pair
                float va = s->u.xrow[cur][gi1];
                float vb = s->u.xrow[cur][gi2];
                s->xmPair[gk][sb*2 + gh] = pk2(va, vb);
            }
            if (sb < BPT-1) {
                ((float4*)s->u.xrow[1-cur])[2*t]   = p0;
                ((float4*)s->u.xrow[1-cur])[2*t+1] = p1;
                ra = p0; rb = p1;
            }
            __syncthreads();
        }

        // ---- phase 1: lsum = relu(xm@W1^T+bl1) + relu(xm@W2^T+bl2) ----
        ull a1a[4], a1b[4], a2a[4], a2b[4];
        #pragma unroll
        for (int i = 0; i < 4; i++) {
            a1a[i] = pk2(bias1, bias1);  a1b[i] = pk2(bias1b, bias1b);
            a2a[i] = pk2(bias2, bias2);  a2b[i] = pk2(bias2b, bias2b);
        }
        #pragma unroll 4
        for (int k = 0; k < 64; k++) {
            float4 wv = s->w12n[k][jp];
            ull w1a = pk2(wv.x, wv.x), w1b = pk2(wv.y, wv.y);
            ull w2a = pk2(wv.z, wv.z), w2b = pk2(wv.w, wv.w);
            ulonglong2 A01 = *(const ulonglong2*)&s->xmPair[k][rp0];
            ulonglong2 A23 = *(const ulonglong2*)&s->xmPair[k][rp0+2];
            fma2(a1a[0], A01.x, w1a); fma2(a1b[0], A01.x, w1b);
            fma2(a2a[0], A01.x, w2a); fma2(a2b[0], A01.x, w2b);
            fma2(a1a[1], A01.y, w1a); fma2(a1b[1], A01.y, w1b);
            fma2(a2a[1], A01.y, w2a); fma2(a2b[1], A01.y, w2b);
            fma2(a1a[2], A23.x, w1a); fma2(a1b[2], A23.x, w1b);
            fma2(a2a[2], A23.x, w2a); fma2(a2b[2], A23.x, w2b);
            fma2(a1a[3], A23.y, w1a); fma2(a1b[3], A23.y, w1b);
            fma2(a2a[3], A23.y, w2a); fma2(a2b[3], A23.y, w2b);
        }
        {   // vectorized STS.128: row j0's 4 pairs, then row j0+1's
            ulonglong2 s0, s1;
            float2 u0 = up2(a1a[0]), v0 = up2(a2a[0]);
            float2 u1 = up2(a1a[1]), v1u = up2(a2a[1]);
            s0.x = pk2(fmaxf(u0.x,0.f)+fmaxf(v0.x,0.f), fmaxf(u0.y,0.f)+fmaxf(v0.y,0.f));
            s0.y = pk2(fmaxf(u1.x,0.f)+fmaxf(v1u.x,0.f), fmaxf(u1.y,0.f)+fmaxf(v1u.y,0.f));
            float2 u2 = up2(a1a[2]), v2u = up2(a2a[2]);
            float2 u3 = up2(a1a[3]), v3 = up2(a2a[3]);
            s1.x = pk2(fmaxf(u2.x,0.f)+fmaxf(v2u.x,0.f), fmaxf(u2.y,0.f)+fmaxf(v2u.y,0.f));
            s1.y = pk2(fmaxf(u3.x,0.f)+fmaxf(v3.x,0.f), fmaxf(u3.y,0.f)+fmaxf(v3.y,0.f));
            *(ulonglong2*)&s->u.lsumPair[j0][rp0]   = s0;
            *(ulonglong2*)&s->u.lsumPair[j0][rp0+2] = s1;
            float2 w0 = up2(a1b[0]), x0 = up2(a2b[0]);
            float2 w1 = up2(a1b[1]), x1 = up2(a2b[1]);
            s0.x = pk2(fmaxf(w0.x,0.f)+fmaxf(x0.x,0.f), fmaxf(w0.y,0.f)+fmaxf(x0.y,0.f));
            s0.y = pk2(fmaxf(w1.x,0.f)+fmaxf(x1.x,0.f), fmaxf(w1.y,0.f)+fmaxf(x1.y,0.f));
            float2 w2v = up2(a1b[2]), x2 = up2(a2b[2]);
            float2 w3 = up2(a1b[3]), x3 = up2(a2b[3]);
            s1.x = pk2(fmaxf(w2v.x,0.f)+fmaxf(x2.x,0.f), fmaxf(w2v.y,0.f)+fmaxf(x2.y,0.f));
            s1.y = pk2(fmaxf(w3.x,0.f)+fmaxf(x3.x,0.f), fmaxf(w3.y,0.f)+fmaxf(x3.y,0.f));
            *(ulonglong2*)&s->u.lsumPair[j0+1][rp0]   = s0;
            *(ulonglong2*)&s->u.lsumPair[j0+1][rp0+2] = s1;
        }
        __syncthreads();

        // ---- phase 2: A = sigmoid(lsum@Wa^T+ba), xmask=(A+1)*xm, fused conv2 ----
        ull aA0[4], aA1[4];
        #pragma unroll
        for (int i = 0; i < 4; i++) { aA0[i] = pk2(biasA, biasA); aA1[i] = pk2(biasAb, biasAb); }
        #pragma unroll 4
        for (int k = 0; k < 64; k++) {
            float2 wv = s->waN[k][jp];
            ull wa0 = pk2(wv.x, wv.x), wa1 = pk2(wv.y, wv.y);
            ulonglong2 A01 = *(const ulonglong2*)&s->u.lsumPair[k][rp0];
            ulonglong2 A23 = *(const ulonglong2*)&s->u.lsumPair[k][rp0+2];
            fma2(aA0[0], A01.x, wa0); fma2(aA1[0], A01.x, wa1);
            fma2(aA0[1], A01.y, wa0); fma2(aA1[1], A01.y, wa1);
            fma2(aA0[2], A23.x, wa0); fma2(aA1[2], A23.x, wa1);
            fma2(aA0[3], A23.y, wa0); fma2(aA1[3], A23.y, wa1);
        }

        // xmask into registers: xmv[i][e][c], i=pair idx, e=elem in pair, c=col (j0+c)
        float xmv[4][2][2];
        #pragma unroll
        for (int i = 0; i < 4; i++) {
            float2 z0 = up2(aA0[i]), z1 = up2(aA1[i]);
            float2 x0 = up2(s->xmPair[j0][rp0+i]);
            float2 x1 = up2(s->xmPair[j0+1][rp0+i]);
            xmv[i][0][0] = (sigmoidf(z0.x)+1.f)*x0.x;
            xmv[i][1][0] = (sigmoidf(z0.y)+1.f)*x0.y;
            xmv[i][0][1] = (sigmoidf(z1.x)+1.f)*x1.x;
            xmv[i][1][1] = (sigmoidf(z1.y)+1.f)*x1.y;
        }
        // column neighbors from adjacent lanes (lane==jp); zero halo at edges
        float lf[4][2], rt[4][2];
        #pragma unroll
        for (int i = 0; i < 4; i++) {
            #pragma unroll
            for (int e = 0; e < 2; e++) {
                float l = __shfl_up_sync(0xffffffffu,  xmv[i][e][1], 1);
                float r = __shfl_down_sync(0xffffffffu, xmv[i][e][0], 1);
                lf[i][e] = (jp == 0)  ? 0.f : l;
                rt[i][e] = (jp == 31) ? 0.f : r;
            }
        }
        // conv2 + double-tanh, straight from registers; pair p=rp0+i holds
        // g-rows (2*(i&1), 2*(i&1)+1) of batch (rp0>>1)+(i>>1)
        {
            const int sbl = rp0 >> 1;
            #pragma unroll
            for (int oo = 0; oo < 4; oo++) {
                float4 wA = *(const float4*)&s->w2n[oo][0];
                float4 wB = *(const float4*)&s->w2n[oo][4];
                float4 wC = *(const float4*)&s->w2n[oo][8];
                const float wv[12] = {wA.x,wA.y,wA.z,wA.w, wB.x,wB.y,wB.z,wB.w,
                                      wC.x,wC.y,wC.z,wC.w};
                const float bz = s->b2s[oo];
                #pragma unroll
                for (int bb = 0; bb < 2; bb++) {
                    float a0 = bz, a1 = bz;
                    #pragma unroll
                    for (int g = 0; g < 4; g++) {
                        const int i = bb*2 + (g >> 1), e = g & 1;
                        const float xl = lf[i][e], xa = xmv[i][e][0],
                                    xb = xmv[i][e][1], xr = rt[i][e];
                        a0 = fmaf(wv[3*g],   xl, a0);
                        a0 = fmaf(wv[3*g+1], xa, a0);
                        a0 = fmaf(wv[3*g+2], xb, a0);
                        a1 = fmaf(wv[3*g],   xa, a1);
                        a1 = fmaf(wv[3*g+1], xb, a1);
                        a1 = fmaf(wv[3*g+2], xr, a1);
                    }
                    float2 o = make_float2(tanh2(a0), tanh2(a1));
                    *(float2*)&out_bag[(size_t)(b0 + sbl + bb) * (NGc*GLc) + oo*GLc + j0] = o;
                }
            }
        }
        __syncthreads();   // protect xmPair / lsumPair(xrow) before next tile
    }
}

extern "C" void kernel_launch(void* const* d_in, const int* in_sizes, int n_in,
                              void* d_out, int out_size)
{
    const float* x   = (const float*)d_in[0];
    const int*   idx = (const int*)  d_in[1];
    const float* v1  = (const float*)d_in[2];
    const float* g1  = (const float*)d_in[3];
    const float* b1  = (const float*)d_in[4];
    const float* v2  = (const float*)d_in[5];
    const float* g2  = (const float*)d_in[6];
    const float* b2  = (const float*)d_in[7];
    const float* W1  = (const float*)d_in[8];
    const float* bl1 = (const float*)d_in[9];
    const float* W2  = (const float*)d_in[10];
    const float* bl2 = (const float*)d_in[11];
    const float* Wa  = (const float*)d_in[12];
    const float* ba  = (const float*)d_in[13];

    cudaFuncSetAttribute(fused_kernel, cudaFuncAttributeMaxDynamicSharedMemorySize,
                         (int)sizeof(Smem));
    fused_kernel<<<296, NTHREADS, sizeof(Smem)>>>(
        x, idx, v1, g1, b1, v2, g2, b2, W1, bl1, W2, bl2, Wa, ba, (float*)d_out);
}